// round 8
// baseline (speedup 1.0000x reference)
#include <cuda_runtime.h>
#include <cstdint>
#include <cstddef>

// ---------------- configuration ----------------
#define THREADS 512
#define BT 32          // batch rows per CTA
// 4 groups of 128 threads. N=128 GEMMs: group g -> cols [32g, 32g+32), RM=4.
// N=64 GEMMs: (grp&1) -> col half (CN=2), (grp>>1) -> row half (RM=2).

// smem strides (floats); multiples of 4 (16B alignment); stride/4 mod 32
// coprime-ish so 16-lane LDS.128 column walks are conflict-free.
#define LD1 116        // W1^T K=112 pad 116 (29 mod 32, coprime)
#define LD2 132        // W2^T K=128 (33 -> 1 mod 32)
#define LD3 132        // W3^T K=128
#define LDD 68         // Wd1^T/Wd2^T K=64 (17 mod 32, coprime)
#define HS  68         // h stride
#define XS  52         // xm stride (13 mod 32, coprime)
#define ZS  132        // z stride

// smem layout (float offsets)
#define O_W1T 0
#define O_W2T (O_W1T + 128*LD1)
#define O_W3T (O_W2T + 128*LD2)
#define O_WD1 (O_W3T + 64*LD3)
#define O_WD2 (O_WD1 + 64*LDD)
#define O_B1  (O_WD2 + 64*LDD)
#define O_B2  (O_B1 + 128)
#define O_B3  (O_B2 + 128)
#define O_BD1 (O_B3 + 64)
#define O_BD2 (O_BD1 + 64)
#define O_SCL (O_BD2 + 64)
#define O_H   (O_SCL + 64)
#define O_XM  (O_H + BT*HS)
#define O_Z   (O_XM + BT*XS)
#define O_IDX (O_Z + BT*ZS)              // per-step gather indices
#define SMEM_FLOATS (O_IDX + 32)

// packed dual-fp32 FMA (Blackwell f32x2). d.lo += a.lo*b.lo; d.hi += a.hi*b.hi
#define FFMA2(d, a, b) asm("fma.rn.f32x2 %0, %1, %2, %0;" : "+l"(d) : "l"(a), "l"(b))

__device__ __forceinline__ float hadd2(unsigned long long p) {
    float lo, hi;
    asm("mov.b64 {%0,%1}, %2;" : "=f"(lo), "=f"(hi) : "l"(p));
    return lo + hi;
}

// MAC loop: A row-major [RMT][K] (k-contiguous), Bt transposed weights [n][K].
// Per k-quad: all .x products, then all .y (acc reuse distance RMT*CN instrs).
template<int K, int RMT, int LDA, int LDB, int CN>
__device__ __forceinline__ void gemm_acc(const float* __restrict__ A,
                                         const float* __restrict__ Bt,
                                         unsigned long long (&acc)[RMT][CN]) {
#pragma unroll 4
    for (int k = 0; k < K; k += 4) {
        ulonglong2 a[RMT], b[CN];
#pragma unroll
        for (int r = 0; r < RMT; r++)
            a[r] = *reinterpret_cast<const ulonglong2*>(A + r*LDA + k);
#pragma unroll
        for (int c = 0; c < CN; c++)
            b[c] = *reinterpret_cast<const ulonglong2*>(Bt + c*16*LDB + k);
#pragma unroll
        for (int c = 0; c < CN; c++)
#pragma unroll
            for (int r = 0; r < RMT; r++)
                FFMA2(acc[r][c], a[r].x, b[c].x);
#pragma unroll
        for (int c = 0; c < CN; c++)
#pragma unroll
            for (int r = 0; r < RMT; r++)
                FFMA2(acc[r][c], a[r].y, b[c].y);
    }
}

extern "C" __global__ void __launch_bounds__(THREADS, 1)
nsde_kernel(const float* __restrict__ x_path, const float* __restrict__ macro_path,
            const float* __restrict__ t_span, const float* __restrict__ noise,
            const float* __restrict__ W1,  const float* __restrict__ b1,
            const float* __restrict__ W2,  const float* __restrict__ b2,
            const float* __restrict__ W3,  const float* __restrict__ b3,
            const float* __restrict__ Wd1, const float* __restrict__ bd1,
            const float* __restrict__ Wd2, const float* __restrict__ bd2,
            const float* __restrict__ scale,
            const float* __restrict__ Wr1, const float* __restrict__ br1,
            const float* __restrict__ Wr2, const float* __restrict__ br2,
            float* __restrict__ out, int B, int STEPS)
{
    extern __shared__ __align__(16) float sm[];
    const int tid = threadIdx.x;
    const int grp = tid >> 7;        // 0..3
    const int t   = tid & 127;
    const int cx  = t & 15;          // 16 column groups
    const int ry  = t >> 4;          // 8 row groups
    const int b0  = blockIdx.x * BT;

    // N=128 GEMMs: RM=4 rows, CN=2 cols
    const int r0   = ry * 4;               // rows r0..r0+3
    const int cbN  = 32*grp + cx;          // col, +16 for c=1
    // N=64 GEMMs: RM=2 rows, CN=2 cols
    const int rh   = grp >> 1;
    const int r0d  = rh*16 + ry*2;         // rows r0d, r0d+1
    const int cbD  = 32*(grp & 1) + cx;    // col, +16 for c=1

    // ---- one-time: load + transpose weights into smem ----
    for (int i = tid; i < 112*128; i += THREADS) {
        int k = i >> 7, n = i & 127;
        sm[O_W1T + n*LD1 + k] = W1[i];
    }
    for (int i = tid; i < 128*128; i += THREADS) {
        int k = i >> 7, n = i & 127;
        sm[O_W2T + n*LD2 + k] = W2[i];
    }
    for (int i = tid; i < 128*64; i += THREADS) {
        int k = i >> 6, n = i & 63;
        sm[O_W3T + n*LD3 + k] = W3[i];
    }
    for (int i = tid; i < 64*64; i += THREADS) {
        int k = i >> 6, n = i & 63;
        sm[O_WD1 + n*LDD + k] = Wd1[i];
        sm[O_WD2 + n*LDD + k] = Wd2[i];
    }
    if (tid < 128) { sm[O_B1 + tid] = b1[tid]; sm[O_B2 + tid] = b2[tid]; }
    if (tid < 64)  {
        sm[O_B3 + tid] = b3[tid]; sm[O_BD1 + tid] = bd1[tid];
        sm[O_BD2 + tid] = bd2[tid]; sm[O_SCL + tid] = scale[tid];
    }
    for (int i = tid; i < BT*HS; i += THREADS) sm[O_H + i] = 0.0f;

    if (tid < STEPS) {
        float tn = t_span[tid] / t_span[STEPS];
        int idx  = (int)(tn * 255.0f);
        reinterpret_cast<int*>(sm + O_IDX)[tid] = max(0, min(idx, 255));
    }

    const float sqdt = sqrtf(0.05f);

    for (int s = 0; s < STEPS; s++) {
        // ---- prefetch this step's noise (2 rows x 2 cols per thread) ----
        float nz[2][2];
#pragma unroll
        for (int r = 0; r < 2; r++)
#pragma unroll
            for (int c = 0; c < 2; c++)
                nz[r][c] = noise[((size_t)s * B + (b0 + r0d + r)) * 64 + (cbD + 16*c)];

        const int idx = reinterpret_cast<const int*>(sm + O_IDX)[s];

        // ---- gather x_t (32 f/row) and m_t (16 f/row) into XM ----
        for (int i = tid; i < 256; i += THREADS) {
            int r = i >> 3, q = i & 7;
            const float* src = x_path + ((size_t)(b0 + r) * 256 + idx) * 32 + 4*q;
            *reinterpret_cast<float4*>(&sm[O_XM + r*XS + 4*q]) =
                *reinterpret_cast<const float4*>(src);
        }
        for (int i = tid; i < 128; i += THREADS) {
            int r = i >> 2, q = i & 3;
            const float* src = macro_path + ((size_t)(b0 + r) * 256 + idx) * 16 + 4*q;
            *reinterpret_cast<float4*>(&sm[O_XM + r*XS + 32 + 4*q]) =
                *reinterpret_cast<const float4*>(src);
        }
        __syncthreads();   // B0: xm ready; prev step's consumers drained

        // ==== GEMM1: z1 = relu([h|x|m] @ W1 + b1); 32 cols/group, K=112 ====
        {
            unsigned long long acc[4][2] = {};
            gemm_acc<64, 4, HS, LD1, 2>(sm + O_H  + r0*HS, sm + O_W1T + cbN*LD1,      acc);
            gemm_acc<48, 4, XS, LD1, 2>(sm + O_XM + r0*XS, sm + O_W1T + cbN*LD1 + 64, acc);
            // dest Z is dead -> no pre-barrier
#pragma unroll
            for (int c = 0; c < 2; c++) {
                int col = cbN + 16*c;
                float bias = sm[O_B1 + col];
#pragma unroll
                for (int r = 0; r < 4; r++)
                    sm[O_Z + (r0+r)*ZS + col] = fmaxf(hadd2(acc[r][c]) + bias, 0.0f);
            }
        }
        __syncthreads();   // B1: z1 ready

        // ==== GEMM2: z2 = relu(z1 @ W2 + b2), in-place, K=128 ====
        {
            unsigned long long acc[4][2] = {};
            gemm_acc<128, 4, ZS, LD2, 2>(sm + O_Z + r0*ZS, sm + O_W2T + cbN*LD2, acc);
            __syncthreads();   // B2: all z1 reads done
#pragma unroll
            for (int c = 0; c < 2; c++) {
                int col = cbN + 16*c;
                float bias = sm[O_B2 + col];
#pragma unroll
                for (int r = 0; r < 4; r++)
                    sm[O_Z + (r0+r)*ZS + col] = fmaxf(hadd2(acc[r][c]) + bias, 0.0f);
            }
        }
        __syncthreads();   // B3: z2 ready

        // ==== GEMM3 (drift = z2@W3+b3, K=128) + GEMMd1 (zd = relu(h@Wd1+bd1))
        // 2 rows x 2 cols per thread (row half x col half)
        {
            unsigned long long acc3[2][2] = {};
            gemm_acc<128, 2, ZS, LD3, 2>(sm + O_Z + r0d*ZS, sm + O_W3T + cbD*LD3, acc3);
            unsigned long long accd[2][2] = {};
            gemm_acc<64, 2, HS, LDD, 2>(sm + O_H + r0d*HS, sm + O_WD1 + cbD*LDD, accd);
            __syncthreads();   // B4: all z2 reads done -> safe to overwrite Z
#pragma unroll
            for (int c = 0; c < 2; c++) {
                int col = cbD + 16*c;
                float b3v = sm[O_B3 + col];
                float bdv = sm[O_BD1 + col];
#pragma unroll
                for (int r = 0; r < 2; r++) {
                    sm[O_Z + (r0d+r)*ZS + 64 + col] = hadd2(acc3[r][c]) + b3v;  // drift
                    sm[O_Z + (r0d+r)*ZS + col] =
                        fmaxf(hadd2(accd[r][c]) + bdv, 0.0f);                    // zd
                }
            }
        }
        __syncthreads();   // B5: drift (Z[64..127]) + zd (Z[0..63]) ready

        // ==== GEMMd2: diff = scale*sigmoid(zd@Wd2+bd2); Euler h update ====
        {
            unsigned long long acc[2][2] = {};
            gemm_acc<64, 2, ZS, LDD, 2>(sm + O_Z + r0d*ZS, sm + O_WD2 + cbD*LDD, acc);
            // epilogue writes only H (not a source of this GEMM) -> no barrier
#pragma unroll
            for (int c = 0; c < 2; c++) {
                int col = cbD + 16*c;
                float biasd2 = sm[O_BD2 + col];
                float scl    = sm[O_SCL + col];
#pragma unroll
                for (int r = 0; r < 2; r++) {
                    float u    = hadd2(acc[r][c]) + biasd2;
                    float sig  = 1.0f / (1.0f + __expf(-u));
                    float diff = scl * sig;
                    float dft  = sm[O_Z + (r0d+r)*ZS + 64 + col];
                    sm[O_H + (r0d+r)*HS + col] += dft*0.05f + diff*sqdt*nz[r][c];
                }
            }
        }
        // next step's B0 orders H writes before G1 reads and XM overwrite
    }
    __syncthreads();   // final h visible

    // ---- readout: z = relu(h @ Wr1 + br1); out = z @ Wr2 + br2 ----
    for (int i = tid; i < 256; i += THREADS) {   // 32 rows x 8 groups of 4 cols
        int r = i >> 3, g = i & 7;
        float z0 = br1[4*g], z1 = br1[4*g+1], z2 = br1[4*g+2], z3 = br1[4*g+3];
        const float* hrow = sm + O_H + r*HS;
#pragma unroll 4
        for (int k = 0; k < 64; k++) {
            float a = hrow[k];
            float4 w = *reinterpret_cast<const float4*>(Wr1 + k*32 + 4*g);
            z0 += a*w.x; z1 += a*w.y; z2 += a*w.z; z3 += a*w.w;
        }
        sm[O_Z + r*ZS + 4*g + 0] = fmaxf(z0, 0.0f);
        sm[O_Z + r*ZS + 4*g + 1] = fmaxf(z1, 0.0f);
        sm[O_Z + r*ZS + 4*g + 2] = fmaxf(z2, 0.0f);
        sm[O_Z + r*ZS + 4*g + 3] = fmaxf(z3, 0.0f);
    }
    __syncthreads();
    if (tid < 64) {
        int r = tid >> 1, o = tid & 1;
        float acc = br2[o];
#pragma unroll 4
        for (int k = 0; k < 32; k++)
            acc += sm[O_Z + r*ZS + k] * Wr2[2*k + o];
        out[(size_t)o * B + b0 + r] = acc;
    }
}

extern "C" void kernel_launch(void* const* d_in, const int* in_sizes, int n_in,
                              void* d_out, int out_size) {
    const float* x_path     = (const float*)d_in[0];
    const float* macro_path = (const float*)d_in[1];
    const float* t_span     = (const float*)d_in[2];
    const float* noise      = (const float*)d_in[3];
    const float* W1  = (const float*)d_in[4];
    const float* b1  = (const float*)d_in[5];
    const float* W2  = (const float*)d_in[6];
    const float* b2  = (const float*)d_in[7];
    const float* W3  = (const float*)d_in[8];
    const float* b3  = (const float*)d_in[9];
    const float* Wd1 = (const float*)d_in[10];
    const float* bd1 = (const float*)d_in[11];
    const float* Wd2 = (const float*)d_in[12];
    const float* bd2 = (const float*)d_in[13];
    const float* scale = (const float*)d_in[14];
    const float* Wr1 = (const float*)d_in[15];
    const float* br1 = (const float*)d_in[16];
    const float* Wr2 = (const float*)d_in[17];
    const float* br2 = (const float*)d_in[18];
    float* out = (float*)d_out;

    int B     = in_sizes[0] / (256 * 32);   // x_path (B, 256, 32)
    int STEPS = in_sizes[3] / (B * 64);     // noise (STEPS, B, 64)

    size_t smem_bytes = (size_t)SMEM_FLOATS * sizeof(float);
    cudaFuncSetAttribute(nsde_kernel,
                         cudaFuncAttributeMaxDynamicSharedMemorySize,
                         (int)smem_bytes);
    nsde_kernel<<<B / BT, THREADS, smem_bytes>>>(
        x_path, macro_path, t_span, noise,
        W1, b1, W2, b2, W3, b3, Wd1, bd1, Wd2, bd2,
        scale, Wr1, br1, Wr2, br2, out, B, STEPS);
}

// round 9
// speedup vs baseline: 1.2861x; 1.2861x over previous
#include <cuda_runtime.h>
#include <cstdint>
#include <cstddef>

// ---------------- configuration ----------------
#define THREADS 256
#define BT 32          // batch rows per CTA
// Two N-split groups of 128 threads (warps 0-3 = low cols, 4-7 = high cols).
// 3 compute phases/step:
//   P0: G1 (z1, RM4/CN4, K=112) fused with Gd1 (zd accs, RM4/CN2, K=64, shares A=h)
//   P1: zd -> ZD (XM region, now dead) ; G2 (z2, RM4/CN4, K=128)
//   P2: G3 (drift, K=128) fused with Gd2 (diff, K=64); h-update all in registers

// smem strides (floats)
#define LD1 116        // W1^T K=112 pad 116
#define LD2 132        // W2^T K=128
#define LD3 132        // W3^T K=128
#define LDD 68         // Wd1^T/Wd2^T K=64
#define HS  68         // h stride
#define XS  52         // xm stride (48 pad 52)
#define ZDS 68         // zd stride (64 pad 68), aliases XM region
#define ZS  132        // z stride (128 pad 132)

// smem layout (float offsets)
#define O_W1T 0
#define O_W2T (O_W1T + 128*LD1)
#define O_W3T (O_W2T + 128*LD2)
#define O_WD1 (O_W3T + 64*LD3)
#define O_WD2 (O_WD1 + 64*LDD)
#define O_B1  (O_WD2 + 64*LDD)
#define O_B2  (O_B1 + 128)
#define O_B3  (O_B2 + 128)
#define O_BD1 (O_B3 + 64)
#define O_BD2 (O_BD1 + 64)
#define O_SCL (O_BD2 + 64)
#define O_H   (O_SCL + 64)
#define O_XM  (O_H + BT*HS)              // xm gather region, ALIASED by ZD
#define O_ZD  O_XM
#define O_Z   (O_XM + BT*ZDS)            // region sized for the larger user (ZD)
#define O_IDX (O_Z + BT*ZS)
#define SMEM_FLOATS (O_IDX + 32)         // 58,016 floats = 232,064 B (<= 227KB)

// packed dual-fp32 FMA (Blackwell f32x2). d.lo += a.lo*b.lo; d.hi += a.hi*b.hi
#define FFMA2(d, a, b) asm("fma.rn.f32x2 %0, %1, %2, %0;" : "+l"(d) : "l"(a), "l"(b))

__device__ __forceinline__ float hadd2(unsigned long long p) {
    float lo, hi;
    asm("mov.b64 {%0,%1}, %2;" : "=f"(lo), "=f"(hi) : "l"(p));
    return lo + hi;
}

// Plain MAC loop (RMT rows x CN cols), .x pass then .y pass per k-quad.
template<int K, int RMT, int LDA, int LDB, int CN>
__device__ __forceinline__ void gemm_acc(const float* __restrict__ A,
                                         const float* __restrict__ Bt,
                                         unsigned long long (&acc)[RMT][CN]) {
#pragma unroll 4
    for (int k = 0; k < K; k += 4) {
        ulonglong2 a[RMT], b[CN];
#pragma unroll
        for (int r = 0; r < RMT; r++)
            a[r] = *reinterpret_cast<const ulonglong2*>(A + r*LDA + k);
#pragma unroll
        for (int c = 0; c < CN; c++)
            b[c] = *reinterpret_cast<const ulonglong2*>(Bt + c*16*LDB + k);
#pragma unroll
        for (int c = 0; c < CN; c++)
#pragma unroll
            for (int r = 0; r < RMT; r++)
                FFMA2(acc[r][c], a[r].x, b[c].x);
#pragma unroll
        for (int c = 0; c < CN; c++)
#pragma unroll
            for (int r = 0; r < RMT; r++)
                FFMA2(acc[r][c], a[r].y, b[c].y);
    }
}

// Fused MAC, shared A: one A stream feeds two B streams / acc sets.
template<int K, int LDA, int LDB1, int LDB2, int CN1, int CN2>
__device__ __forceinline__ void gemm_fused_sA(const float* __restrict__ A,
                                              const float* __restrict__ B1,
                                              const float* __restrict__ B2,
                                              unsigned long long (&acc1)[4][CN1],
                                              unsigned long long (&acc2)[4][CN2]) {
#pragma unroll 4
    for (int k = 0; k < K; k += 4) {
        ulonglong2 a[4], b1r[CN1], b2r[CN2];
#pragma unroll
        for (int r = 0; r < 4; r++)
            a[r] = *reinterpret_cast<const ulonglong2*>(A + r*LDA + k);
#pragma unroll
        for (int c = 0; c < CN1; c++)
            b1r[c] = *reinterpret_cast<const ulonglong2*>(B1 + c*16*LDB1 + k);
#pragma unroll
        for (int c = 0; c < CN2; c++)
            b2r[c] = *reinterpret_cast<const ulonglong2*>(B2 + c*16*LDB2 + k);
#pragma unroll
        for (int c = 0; c < CN1; c++)
#pragma unroll
            for (int r = 0; r < 4; r++) FFMA2(acc1[r][c], a[r].x, b1r[c].x);
#pragma unroll
        for (int c = 0; c < CN2; c++)
#pragma unroll
            for (int r = 0; r < 4; r++) FFMA2(acc2[r][c], a[r].x, b2r[c].x);
#pragma unroll
        for (int c = 0; c < CN1; c++)
#pragma unroll
            for (int r = 0; r < 4; r++) FFMA2(acc1[r][c], a[r].y, b1r[c].y);
#pragma unroll
        for (int c = 0; c < CN2; c++)
#pragma unroll
            for (int r = 0; r < 4; r++) FFMA2(acc2[r][c], a[r].y, b2r[c].y);
    }
}

// Fused MAC, two independent A/B streams (RM=4, CN=2 each).
template<int K, int LDA1, int LDA2, int LDB1, int LDB2>
__device__ __forceinline__ void gemm_fused_2A(const float* __restrict__ A1,
                                              const float* __restrict__ A2,
                                              const float* __restrict__ B1,
                                              const float* __restrict__ B2,
                                              unsigned long long (&acc1)[4][2],
                                              unsigned long long (&acc2)[4][2]) {
#pragma unroll 4
    for (int k = 0; k < K; k += 4) {
        ulonglong2 a1[4], a2[4], b1r[2], b2r[2];
#pragma unroll
        for (int r = 0; r < 4; r++) {
            a1[r] = *reinterpret_cast<const ulonglong2*>(A1 + r*LDA1 + k);
            a2[r] = *reinterpret_cast<const ulonglong2*>(A2 + r*LDA2 + k);
        }
#pragma unroll
        for (int c = 0; c < 2; c++) {
            b1r[c] = *reinterpret_cast<const ulonglong2*>(B1 + c*16*LDB1 + k);
            b2r[c] = *reinterpret_cast<const ulonglong2*>(B2 + c*16*LDB2 + k);
        }
#pragma unroll
        for (int c = 0; c < 2; c++)
#pragma unroll
            for (int r = 0; r < 4; r++) FFMA2(acc1[r][c], a1[r].x, b1r[c].x);
#pragma unroll
        for (int c = 0; c < 2; c++)
#pragma unroll
            for (int r = 0; r < 4; r++) FFMA2(acc2[r][c], a2[r].x, b2r[c].x);
#pragma unroll
        for (int c = 0; c < 2; c++)
#pragma unroll
            for (int r = 0; r < 4; r++) FFMA2(acc1[r][c], a1[r].y, b1r[c].y);
#pragma unroll
        for (int c = 0; c < 2; c++)
#pragma unroll
            for (int r = 0; r < 4; r++) FFMA2(acc2[r][c], a2[r].y, b2r[c].y);
    }
}

extern "C" __global__ void __launch_bounds__(THREADS, 1)
nsde_kernel(const float* __restrict__ x_path, const float* __restrict__ macro_path,
            const float* __restrict__ t_span, const float* __restrict__ noise,
            const float* __restrict__ W1,  const float* __restrict__ b1,
            const float* __restrict__ W2,  const float* __restrict__ b2,
            const float* __restrict__ W3,  const float* __restrict__ b3,
            const float* __restrict__ Wd1, const float* __restrict__ bd1,
            const float* __restrict__ Wd2, const float* __restrict__ bd2,
            const float* __restrict__ scale,
            const float* __restrict__ Wr1, const float* __restrict__ br1,
            const float* __restrict__ Wr2, const float* __restrict__ br2,
            float* __restrict__ out, int B, int STEPS)
{
    extern __shared__ __align__(16) float sm[];
    const int tid = threadIdx.x;
    const int grp = tid >> 7;        // 0 = low col half, 1 = high col half
    const int t   = tid & 127;
    const int cx  = t & 15;
    const int ry  = t >> 4;
    const int r0  = ry * 4;          // rows r0..r0+3 (all phases)
    const int b0  = blockIdx.x * BT;
    const int cbN = 64*grp + cx;     // N=128 GEMMs: col, +16 per c (CN=4)
    const int cbD = 32*grp + cx;     // N=64 GEMMs: col, +16 per c (CN=2)

    // ---- one-time: load + transpose weights into smem ----
    for (int i = tid; i < 112*128; i += THREADS) {
        int k = i >> 7, n = i & 127;
        sm[O_W1T + n*LD1 + k] = W1[i];
    }
    for (int i = tid; i < 128*128; i += THREADS) {
        int k = i >> 7, n = i & 127;
        sm[O_W2T + n*LD2 + k] = W2[i];
    }
    for (int i = tid; i < 128*64; i += THREADS) {
        int k = i >> 6, n = i & 63;
        sm[O_W3T + n*LD3 + k] = W3[i];
    }
    for (int i = tid; i < 64*64; i += THREADS) {
        int k = i >> 6, n = i & 63;
        sm[O_WD1 + n*LDD + k] = Wd1[i];
        sm[O_WD2 + n*LDD + k] = Wd2[i];
    }
    if (tid < 128) { sm[O_B1 + tid] = b1[tid]; sm[O_B2 + tid] = b2[tid]; }
    if (tid < 64)  {
        sm[O_B3 + tid] = b3[tid]; sm[O_BD1 + tid] = bd1[tid];
        sm[O_BD2 + tid] = bd2[tid]; sm[O_SCL + tid] = scale[tid];
    }
    for (int i = tid; i < BT*HS; i += THREADS) sm[O_H + i] = 0.0f;

    if (tid < STEPS) {
        float tn = t_span[tid] / t_span[STEPS];
        int idx  = (int)(tn * 255.0f);
        reinterpret_cast<int*>(sm + O_IDX)[tid] = max(0, min(idx, 255));
    }
    __syncthreads();   // init visible (IDX, weights, h)

    const float sqdt = sqrtf(0.05f);

    for (int s = 0; s < STEPS; s++) {
        // ---- prefetch this step's noise (4 rows x 2 cols, own block) ----
        float nz[4][2];
#pragma unroll
        for (int r = 0; r < 4; r++)
#pragma unroll
            for (int c = 0; c < 2; c++)
                nz[r][c] = noise[((size_t)s * B + (b0 + r0 + r)) * 64 + (cbD + 16*c)];

        const int idx = reinterpret_cast<const int*>(sm + O_IDX)[s];

        // ---- gather x_t / m_t into XM (safe: ZD readers drained at loop-end barrier)
        for (int i = tid; i < 256; i += THREADS) {
            int r = i >> 3, q = i & 7;
            const float* src = x_path + ((size_t)(b0 + r) * 256 + idx) * 32 + 4*q;
            *reinterpret_cast<float4*>(&sm[O_XM + r*XS + 4*q]) =
                *reinterpret_cast<const float4*>(src);
        }
        for (int i = tid; i < 128; i += THREADS) {
            int r = i >> 2, q = i & 3;
            const float* src = macro_path + ((size_t)(b0 + r) * 256 + idx) * 16 + 4*q;
            *reinterpret_cast<float4*>(&sm[O_XM + r*XS + 32 + 4*q]) =
                *reinterpret_cast<const float4*>(src);
        }
        __syncthreads();   // B0: xm ready, h stable

        // ==== P0: G1 (z1) fused with Gd1 (zd accs), shared A = h ====
        unsigned long long accd[4][2] = {};    // zd partials, live through P1
        {
            unsigned long long acc[4][4] = {};
            gemm_fused_sA<64, HS, LD1, LDD, 4, 2>(
                sm + O_H + r0*HS, sm + O_W1T + cbN*LD1, sm + O_WD1 + cbD*LDD,
                acc, accd);
            gemm_acc<48, 4, XS, LD1, 4>(sm + O_XM + r0*XS,
                                        sm + O_W1T + cbN*LD1 + 64, acc);
#pragma unroll
            for (int c = 0; c < 4; c++) {
                int col = cbN + 16*c;
                float bias = sm[O_B1 + col];
#pragma unroll
                for (int r = 0; r < 4; r++)
                    sm[O_Z + (r0+r)*ZS + col] = fmaxf(hadd2(acc[r][c]) + bias, 0.0f);
            }
        }
        __syncthreads();   // B1: z1 ready; all XM reads complete

        // ==== P1: finalize zd -> ZD (XM region, now dead); G2 (z2) ====
        {
#pragma unroll
            for (int c = 0; c < 2; c++) {
                int col = cbD + 16*c;
                float bdv = sm[O_BD1 + col];
#pragma unroll
                for (int r = 0; r < 4; r++)
                    sm[O_ZD + (r0+r)*ZDS + col] =
                        fmaxf(hadd2(accd[r][c]) + bdv, 0.0f);
            }
            unsigned long long acc[4][4] = {};
            gemm_acc<128, 4, ZS, LD2, 4>(sm + O_Z + r0*ZS, sm + O_W2T + cbN*LD2, acc);
            __syncthreads();   // B2: z1 reads done; zd stores done
#pragma unroll
            for (int c = 0; c < 4; c++) {
                int col = cbN + 16*c;
                float bias = sm[O_B2 + col];
#pragma unroll
                for (int r = 0; r < 4; r++)
                    sm[O_Z + (r0+r)*ZS + col] = fmaxf(hadd2(acc[r][c]) + bias, 0.0f);
            }
        }
        __syncthreads();   // B3: z2 ready; zd visible

        // ==== P2: G3 (drift) fused with Gd2 (diff); h update in registers ====
        {
            unsigned long long acc3[4][2] = {};
            unsigned long long acc2[4][2] = {};
            gemm_fused_2A<64, ZS, ZDS, LD3, LDD>(
                sm + O_Z + r0*ZS, sm + O_ZD + r0*ZDS,
                sm + O_W3T + cbD*LD3, sm + O_WD2 + cbD*LDD,
                acc3, acc2);
            gemm_acc<64, 4, ZS, LD3, 2>(sm + O_Z + r0*ZS + 64,
                                        sm + O_W3T + cbD*LD3 + 64, acc3);
#pragma unroll
            for (int c = 0; c < 2; c++) {
                int col = cbD + 16*c;
                float b3v = sm[O_B3 + col];
                float bdv = sm[O_BD2 + col];
                float scl = sm[O_SCL + col];
#pragma unroll
                for (int r = 0; r < 4; r++) {
                    float drift = hadd2(acc3[r][c]) + b3v;
                    float u     = hadd2(acc2[r][c]) + bdv;
                    float sig   = 1.0f / (1.0f + __expf(-u));
                    sm[O_H + (r0+r)*HS + col] +=
                        drift*0.05f + scl*sig*sqdt*nz[r][c];
                }
            }
        }
        __syncthreads();   // B4: ZD/Z readers drained; H updates visible
    }

    // ---- readout: z = relu(h @ Wr1 + br1); out = z @ Wr2 + br2 ----
    for (int i = tid; i < 256; i += THREADS) {   // 32 rows x 8 groups of 4 cols
        int r = i >> 3, g = i & 7;
        float z0 = br1[4*g], z1 = br1[4*g+1], z2 = br1[4*g+2], z3 = br1[4*g+3];
        const float* hrow = sm + O_H + r*HS;
#pragma unroll 4
        for (int k = 0; k < 64; k++) {
            float a = hrow[k];
            float4 w = *reinterpret_cast<const float4*>(Wr1 + k*32 + 4*g);
            z0 += a*w.x; z1 += a*w.y; z2 += a*w.z; z3 += a*w.w;
        }
        sm[O_Z + r*ZS + 4*g + 0] = fmaxf(z0, 0.0f);
        sm[O_Z + r*ZS + 4*g + 1] = fmaxf(z1, 0.0f);
        sm[O_Z + r*ZS + 4*g + 2] = fmaxf(z2, 0.0f);
        sm[O_Z + r*ZS + 4*g + 3] = fmaxf(z3, 0.0f);
    }
    __syncthreads();
    if (tid < 64) {
        int r = tid >> 1, o = tid & 1;
        float acc = br2[o];
#pragma unroll 4
        for (int k = 0; k < 32; k++)
            acc += sm[O_Z + r*ZS + k] * Wr2[2*k + o];
        out[(size_t)o * B + b0 + r] = acc;
    }
}

extern "C" void kernel_launch(void* const* d_in, const int* in_sizes, int n_in,
                              void* d_out, int out_size) {
    const float* x_path     = (const float*)d_in[0];
    const float* macro_path = (const float*)d_in[1];
    const float* t_span     = (const float*)d_in[2];
    const float* noise      = (const float*)d_in[3];
    const float* W1  = (const float*)d_in[4];
    const float* b1  = (const float*)d_in[5];
    const float* W2  = (const float*)d_in[6];
    const float* b2  = (const float*)d_in[7];
    const float* W3  = (const float*)d_in[8];
    const float* b3  = (const float*)d_in[9];
    const float* Wd1 = (const float*)d_in[10];
    const float* bd1 = (const float*)d_in[11];
    const float* Wd2 = (const float*)d_in[12];
    const float* bd2 = (const float*)d_in[13];
    const float* scale = (const float*)d_in[14];
    const float* Wr1 = (const float*)d_in[15];
    const float* br1 = (const float*)d_in[16];
    const float* Wr2 = (const float*)d_in[17];
    const float* br2 = (const float*)d_in[18];
    float* out = (float*)d_out;

    int B     = in_sizes[0] / (256 * 32);   // x_path (B, 256, 32)
    int STEPS = in_sizes[3] / (B * 64);     // noise (STEPS, B, 64)

    size_t smem_bytes = (size_t)SMEM_FLOATS * sizeof(float);
    cudaFuncSetAttribute(nsde_kernel,
                         cudaFuncAttributeMaxDynamicSharedMemorySize,
                         (int)smem_bytes);
    nsde_kernel<<<B / BT, THREADS, smem_bytes>>>(
        x_path, macro_path, t_span, noise,
        W1, b1, W2, b2, W3, b3, Wd1, bd1, Wd2, bd2,
        scale, Wr1, br1, Wr2, br2, out, B, STEPS);
}